// round 10
// baseline (speedup 1.0000x reference)
#include <cuda_runtime.h>
#include <cuda_fp16.h>
#include <cstdint>

// ============================================================================
// y = x @ W_binT - rowmean(y),  B=131072, IN=OUT=256.
// Trick 1: fold mean into weights: W' = W_bin - c/256 (EXACT in fp16).
// Trick 2: single fp16 pass for x (rel err ~2e-4 << 1e-3).
// R10: BARRIER-FREE main loop. A fragments loaded straight from GMEM into
//      mma register layout (no A smem / STS / A-ldmatrix / __syncthreads):
//      enabled by permuting W's K-columns so physical x order 4q+2h+b maps
//      to logical k 2q+8h+b (same perm on both operands => invariant).
//      Warps fully independent -> no bulk-sync stall (the ~7k cyc/tile gap
//      that survived R4..R9). R9 sector-aligned output row-perm kept.
// ============================================================================

static constexpr int INF    = 256;
static constexpr int OUTF   = 256;
static constexpr int BATCH  = 131072;
static constexpr int MTILE  = 128;
static constexpr int NTILES = BATCH / MTILE;   // 1024
static constexpr int GRID   = 148;
static constexpr int THREADS = 256;

static constexpr int PW = 264;   // W smem pitch (halfs), conflict-free for ldmatrix
static constexpr int WBYTES = OUTF * PW * 2;        // 135168
static constexpr int SMEM_TOTAL = WBYTES;

__device__ __half g_wprep[OUTF * PW];   // mean-folded W', row+col permuted

// ---------------------------------------------------------------------------
// fused prep: one block per input column i, thread t = output row o.
//  value: v = bin(w[o][i]) - cnt(i)/256   (exact in fp16)
//  ROW permutation (R9, sector-aligned epilogue):
//    rem=o&63: j=rem>>4, q=(rem>>2)&3, e=rem&3
//    pos = (o&~63) | (j*16 + (e>>1)*8 + q*2 + (e&1))
//  COLUMN permutation (R10, direct-LDG A fragments):
//    r=i&15: q=r>>2, h=(r>>1)&1, b=r&1
//    col = (i&~15) | (q*2 + h*8 + b)
// ---------------------------------------------------------------------------
__global__ void prep_k(const float* __restrict__ w) {
    __shared__ int red[256];
    const int i = blockIdx.x, t = threadIdx.x;
    const int bin = (w[t * INF + i] > 0.8f) ? 1 : 0;
    red[t] = bin;
    __syncthreads();
    #pragma unroll
    for (int s = 128; s > 0; s >>= 1) {
        if (t < s) red[t] += red[t + s];
        __syncthreads();
    }
    const float v = (float)bin - (float)red[0] * (1.0f / 256.0f);
    const int rem = t & 63;
    const int j  = rem >> 4;
    const int qo = (rem >> 2) & 3;
    const int e  = rem & 3;
    const int pos = (t & ~63) | (j * 16 + (e >> 1) * 8 + qo * 2 + (e & 1));
    const int r  = i & 15;
    const int qk = r >> 2;
    const int h  = (r >> 1) & 1;
    const int b  = r & 1;
    const int col = (i & ~15) | (qk * 2 + h * 8 + b);
    g_wprep[pos * PW + col] = __float2half_rn(v);
}

// ---------------------------------------------------------------------------
// main GEMM
// ---------------------------------------------------------------------------
#define MMA_F16(c, a, b0, b1)                                                  \
    asm volatile(                                                              \
        "mma.sync.aligned.m16n8k16.row.col.f32.f16.f16.f32 "                   \
        "{%0,%1,%2,%3},{%4,%5,%6,%7},{%8,%9},{%0,%1,%2,%3};"                   \
        : "+f"((c)[0]), "+f"((c)[1]), "+f"((c)[2]), "+f"((c)[3])               \
        : "r"((a)[0]), "r"((a)[1]), "r"((a)[2]), "r"((a)[3]),                  \
          "r"(b0), "r"(b1))

#define LDSM4(r, addr)                                                         \
    asm volatile("ldmatrix.sync.aligned.m8n8.x4.shared.b16 {%0,%1,%2,%3}, [%4];" \
        : "=r"((r)[0]), "=r"((r)[1]), "=r"((r)[2]), "=r"((r)[3]) : "r"(addr))

__global__ void __launch_bounds__(THREADS, 1)
bgemm_kernel(const float* __restrict__ x, float* __restrict__ out)
{
    extern __shared__ char smem[];
    const int tid  = threadIdx.x;
    const int lane = tid & 31;
    const int wid  = tid >> 5;
    const int wm   = (wid & 1) * 64;   // warp m-offset (2-way)
    const int wn   = (wid >> 1) * 64;  // warp n-offset (4-way)

    // ---- resident W' into smem (only barrier in the kernel)
    {
        const uint4* src = reinterpret_cast<const uint4*>(g_wprep);
        uint4* dst = reinterpret_cast<uint4*>(smem);
        for (int idx = tid; idx < WBYTES / 16; idx += THREADS)
            dst[idx] = src[idx];
    }
    __syncthreads();

    uint32_t sb;
    asm("{ .reg .u64 t; cvta.to.shared.u64 t, %1; cvt.u32.u64 %0, t; }"
        : "=r"(sb) : "l"(smem));

    // B ldmatrix source offset (bytes), unchanged geometry
    const uint32_t boff =
        (uint32_t)((wn + ((lane >> 4) & 1) * 8 + (lane & 7)) * PW +
                   ((lane >> 3) & 1) * 8) * 2u;

    // A direct-LDG base: row = wm + (lane>>2), col nibble = (lane&3)*4.
    // Per (mi, hh): +((mi*16 + hh*8) * INF); per k16 step: +16.
    const int g = lane >> 2;
    const int q = lane & 3;
    const float* gA0 = x + ((size_t)blockIdx.x * MTILE + wm + g) * INF + q * 4;
    const size_t tileStep = (size_t)GRID * MTILE * INF;

    float4 xr[8];     // landing buffer for one k16-step: (mi, row/row+8)

    auto lda = [&](const float* base, int kk) {
        const float* p = base + kk * 16;
        #pragma unroll
        for (int mi = 0; mi < 4; ++mi) {
            #pragma unroll
            for (int hh = 0; hh < 2; ++hh) {
                float4 v;
                asm volatile("ld.global.ca.v4.f32 {%0,%1,%2,%3}, [%4];"
                             : "=f"(v.x), "=f"(v.y), "=f"(v.z), "=f"(v.w)
                             : "l"(p + (size_t)(mi * 16 + hh * 8) * INF));
                xr[mi * 2 + hh] = v;
            }
        }
    };

    const float* gA = gA0;
    lda(gA, 0);   // prologue: k-step 0 of first tile

    for (int tile = blockIdx.x; tile < NTILES; tile += GRID) {
        float acc[4][8][4];
        #pragma unroll
        for (int a = 0; a < 4; ++a)
            #pragma unroll
            for (int b = 0; b < 8; ++b)
                #pragma unroll
                for (int c = 0; c < 4; ++c) acc[a][b][c] = 0.0f;

        const bool lastTile = (tile + GRID >= NTILES);

        #pragma unroll 4
        for (int kk = 0; kk < 16; ++kk) {
            // convert landed fp32 -> fragment regs
            // af[mi]: reg0=(row g, f0f1) reg1=(row g+8, f0f1)
            //         reg2=(row g, f2f3) reg3=(row g+8, f2f3)
            uint32_t af[4][4];
            #pragma unroll
            for (int mi = 0; mi < 4; ++mi) {
                const float4 v0 = xr[mi * 2];
                const float4 v1 = xr[mi * 2 + 1];
                asm("cvt.rn.f16x2.f32 %0, %1, %2;" : "=r"(af[mi][0]) : "f"(v0.y), "f"(v0.x));
                asm("cvt.rn.f16x2.f32 %0, %1, %2;" : "=r"(af[mi][1]) : "f"(v1.y), "f"(v1.x));
                asm("cvt.rn.f16x2.f32 %0, %1, %2;" : "=r"(af[mi][2]) : "f"(v0.w), "f"(v0.z));
                asm("cvt.rn.f16x2.f32 %0, %1, %2;" : "=r"(af[mi][3]) : "f"(v1.w), "f"(v1.z));
            }

            // issue next k-step's A loads (wraps to next tile's k0)
            if (kk < 15)            lda(gA, kk + 1);
            else if (!lastTile)     lda(gA + tileStep, 0);

            // B fragments
            uint32_t bfr[4][4];
            const uint32_t kb = (uint32_t)(kk * 16) * 2u;
            #pragma unroll
            for (int np = 0; np < 4; ++np)
                LDSM4(bfr[np], sb + boff + (uint32_t)(np * 16 * PW * 2) + kb);

            // 32 MMAs
            #pragma unroll
            for (int mi = 0; mi < 4; ++mi)
                #pragma unroll
                for (int ni = 0; ni < 8; ++ni)
                    MMA_F16(acc[mi][ni], af[mi],
                            bfr[ni >> 1][(ni & 1) * 2],
                            bfr[ni >> 1][(ni & 1) * 2 + 1]);
        }
        gA += tileStep;

        // ---- epilogue: sector-aligned permuted stores (R9 layout).
        #pragma unroll
        for (int mi = 0; mi < 4; ++mi) {
            const size_t rbase = (size_t)(tile * MTILE + wm + mi * 16);
            float* p0 = out + (rbase + g)     * OUTF + wn + q * 4;
            float* p1 = out + (rbase + g + 8) * OUTF + wn + q * 4;
            #pragma unroll
            for (int j = 0; j < 4; ++j) {
                asm volatile("st.global.cs.v4.f32 [%0], {%1,%2,%3,%4};"
                             :: "l"(p0 + j * 16),
                                "f"(acc[mi][2*j][0]), "f"(acc[mi][2*j][1]),
                                "f"(acc[mi][2*j+1][0]), "f"(acc[mi][2*j+1][1]));
                asm volatile("st.global.cs.v4.f32 [%0], {%1,%2,%3,%4};"
                             :: "l"(p1 + j * 16),
                                "f"(acc[mi][2*j][2]), "f"(acc[mi][2*j][3]),
                                "f"(acc[mi][2*j+1][2]), "f"(acc[mi][2*j+1][3]));
            }
        }
    }
}

// ---------------------------------------------------------------------------
extern "C" void kernel_launch(void* const* d_in, const int* in_sizes, int n_in,
                              void* d_out, int out_size) {
    const float* x = (const float*)d_in[0];
    const float* w = (const float*)d_in[1];
    if (n_in >= 2 && in_sizes[0] < in_sizes[1]) {  // defensive: x is the big one
        const float* t = x; x = w; w = t;
    }
    float* out = (float*)d_out;

    prep_k<<<256, 256>>>(w);

    cudaFuncSetAttribute(bgemm_kernel,
                         cudaFuncAttributeMaxDynamicSharedMemorySize, SMEM_TOTAL);
    bgemm_kernel<<<GRID, THREADS, SMEM_TOTAL>>>(x, out);
}

// round 12
// speedup vs baseline: 1.2080x; 1.2080x over previous
#include <cuda_runtime.h>
#include <cuda_fp16.h>
#include <cstdint>

// ============================================================================
// y = x @ W_binT - rowmean(y),  B=131072, IN=OUT=256.
// Trick 1: fold mean into weights: W' = W_bin - c/256 (EXACT in fp16).
// Trick 2: single fp16 pass for x (rel err ~2e-4 << 1e-3).
// R11: 2 CTAs/SM via N-split. Each CTA: 128 threads / 4 warps, output tile
//      128M x 128N, warp tile 64x64 (proven shape). Two independent CTAs
//      per SM overlap each other's barrier/load/epilogue phases -- the
//      cross-phase stall that every intra-CTA variant (R5-R10) failed to
//      hide. x is read twice but the 2nd read L2-hits (pair CTAs share the
//      M-tile). R9 sector-aligned permuted epilogue kept.
// ============================================================================

static constexpr int INF    = 256;
static constexpr int OUTF   = 256;
static constexpr int BATCH  = 131072;
static constexpr int MTILE  = 128;
static constexpr int NTILES = BATCH / MTILE;   // 1024
static constexpr int GRID   = 148;             // tile stride (CTA pairs)
static constexpr int THREADS = 128;

static constexpr int PW = 264;   // W smem pitch (halfs), conflict-free for ldmatrix
static constexpr int PA = 40;    // A smem pitch (halfs) for K32 chunks; 20r%32 distinct
static constexpr int WROWS   = 128;                  // N-half rows of W' per CTA
static constexpr int WBYTES_H = WROWS * PW * 2;      // 67584
static constexpr int ABYTES  = MTILE * PA * 2;       // 10240 (one 128x32 chunk)
static constexpr int SMEM_TOTAL = WBYTES_H + 2 * ABYTES;  // 88064 -> 2 CTAs/SM

__device__ __half g_wprep[OUTF * PW];   // mean-folded W', row-permuted

// ---------------------------------------------------------------------------
// fused prep (unchanged from R9): one block per input column i, thread t = o.
//  ROW permutation for sector-aligned epilogue:
//    rem=o&63: j=rem>>4, q=(rem>>2)&3, e=rem&3
//    pos = (o&~63) | (j*16 + (e>>1)*8 + q*2 + (e&1))
// ---------------------------------------------------------------------------
__global__ void prep_k(const float* __restrict__ w) {
    __shared__ int red[256];
    const int i = blockIdx.x, t = threadIdx.x;
    const int bin = (w[t * INF + i] > 0.8f) ? 1 : 0;
    red[t] = bin;
    __syncthreads();
    #pragma unroll
    for (int s = 128; s > 0; s >>= 1) {
        if (t < s) red[t] += red[t + s];
        __syncthreads();
    }
    const float v = (float)bin - (float)red[0] * (1.0f / 256.0f);
    const int rem = t & 63;
    const int j = rem >> 4;
    const int q = (rem >> 2) & 3;
    const int e = rem & 3;
    const int pos = (t & ~63) | (j * 16 + (e >> 1) * 8 + q * 2 + (e & 1));
    g_wprep[pos * PW + i] = __float2half_rn(v);
}

// ---------------------------------------------------------------------------
// main GEMM
// ---------------------------------------------------------------------------
#define MMA_F16(c, a, b0, b1)                                                  \
    asm volatile(                                                              \
        "mma.sync.aligned.m16n8k16.row.col.f32.f16.f16.f32 "                   \
        "{%0,%1,%2,%3},{%4,%5,%6,%7},{%8,%9},{%0,%1,%2,%3};"                   \
        : "+f"((c)[0]), "+f"((c)[1]), "+f"((c)[2]), "+f"((c)[3])               \
        : "r"((a)[0]), "r"((a)[1]), "r"((a)[2]), "r"((a)[3]),                  \
          "r"(b0), "r"(b1))

#define LDSM4(r, addr)                                                         \
    asm volatile("ldmatrix.sync.aligned.m8n8.x4.shared.b16 {%0,%1,%2,%3}, [%4];" \
        : "=r"((r)[0]), "=r"((r)[1]), "=r"((r)[2]), "=r"((r)[3]) : "r"(addr))

__global__ void __launch_bounds__(THREADS, 2)
bgemm_kernel(const float* __restrict__ x, float* __restrict__ out)
{
    extern __shared__ char smem[];
    const int tid   = threadIdx.x;
    const int lane  = tid & 31;
    const int wid   = tid >> 5;          // 0..3
    const int wm    = (wid & 1) * 64;    // warp m-offset (2-way)
    const int wn    = (wid >> 1) * 64;   // warp n-offset within half (2-way)
    const int nhalf = blockIdx.x & 1;    // which 128-col output half
    const int tile0 = blockIdx.x >> 1;   // starting M-tile

    // ---- resident W' half into smem (whole kernel lifetime)
    {
        const uint4* src = reinterpret_cast<const uint4*>(
            g_wprep + (size_t)nhalf * WROWS * PW);
        uint4* dst = reinterpret_cast<uint4*>(smem);
        for (int idx = tid; idx < WBYTES_H / 16; idx += THREADS)
            dst[idx] = src[idx];
    }

    uint32_t sb;
    asm("{ .reg .u64 t; cvta.to.shared.u64 t, %1; cvt.u32.u64 %0, t; }"
        : "=r"(sb) : "l"(smem));
    const uint32_t ABUF[2] = { sb + WBYTES_H, sb + WBYTES_H + ABYTES };

    // per-thread ldmatrix source offsets (bytes)
    const uint32_t aoff =
        (uint32_t)((wm + (lane & 15)) * PA + (lane >> 4) * 8) * 2u;
    const uint32_t boff =
        (uint32_t)((wn + ((lane >> 4) & 1) * 8 + (lane & 7)) * PW +
                   ((lane >> 3) & 1) * 8) * 2u;

    // flat-index x mapping for a 128x32 chunk: 1024 float4, 128 threads ->
    // 8 float4/thread: row = (tid>>3) + 16*j, col4 = tid&7.
    const int arow0 = tid >> 3;         // 0..15
    const int acol4 = tid & 7;          // 0..7

    float4 xr[8];

    auto ldg_chunk = [&](int nt, int nc) {
        if (nt < NTILES) {
            const float* gp = x + ((size_t)nt * MTILE + arow0) * INF
                               + nc * 32 + acol4 * 4;
            #pragma unroll
            for (int j = 0; j < 8; ++j) {
                float4 v;
                asm volatile("ld.global.v4.f32 {%0,%1,%2,%3}, [%4];"
                             : "=f"(v.x), "=f"(v.y), "=f"(v.z), "=f"(v.w)
                             : "l"(gp + (size_t)j * 16 * INF));
                xr[j] = v;
            }
        }
    };
    auto sts_chunk = [&](uint32_t ab) {
        const uint32_t base = ab + (uint32_t)(arow0 * PA + acol4 * 4) * 2u;
        #pragma unroll
        for (int j = 0; j < 8; ++j) {
            uint32_t h0, h1;
            asm("cvt.rn.f16x2.f32 %0, %1, %2;" : "=r"(h0) : "f"(xr[j].y), "f"(xr[j].x));
            asm("cvt.rn.f16x2.f32 %0, %1, %2;" : "=r"(h1) : "f"(xr[j].w), "f"(xr[j].z));
            asm volatile("st.shared.v2.b32 [%0], {%1,%2};"
                         :: "r"(base + (uint32_t)(j * 16 * PA) * 2u), "r"(h0), "r"(h1));
        }
    };

    // prologue: chunk0 -> buf0; preload chunk1 regs
    ldg_chunk(tile0, 0);
    sts_chunk(ABUF[0]);
    ldg_chunk(tile0, 1);
    __syncthreads();

    for (int tile = tile0; tile < NTILES; tile += GRID) {
        float acc[4][8][4];
        #pragma unroll
        for (int a = 0; a < 4; ++a)
            #pragma unroll
            for (int b = 0; b < 8; ++b)
                #pragma unroll
                for (int c = 0; c < 4; ++c) acc[a][b][c] = 0.0f;

        #pragma unroll
        for (int ch = 0; ch < 8; ++ch) {
            // STS chunk ch+1 (regs already loaded) into the other buffer
            const bool has_next = !(ch == 7 && tile + GRID >= NTILES);
            if (has_next) sts_chunk(ABUF[(ch + 1) & 1]);

            // prefetch regs for chunk ch+2
            {
                int nt = tile, nc = ch + 2;
                if (nc >= 8) { nc -= 8; nt += GRID; }
                ldg_chunk(nt, nc);
            }

            // MMA over chunk ch (2 k16-steps) from buf[ch&1]
            const uint32_t AB  = ABUF[ch & 1];
            const uint32_t bko = (uint32_t)(ch * 32) * 2u;
            #pragma unroll
            for (int ks = 0; ks < 2; ++ks) {
                const uint32_t kb2 = (uint32_t)(ks * 16) * 2u;
                uint32_t bfr[4][4];
                #pragma unroll
                for (int np = 0; np < 4; ++np)
                    LDSM4(bfr[np], sb + boff + (uint32_t)(np * 16 * PW * 2) + bko + kb2);
                uint32_t af[4][4];
                #pragma unroll
                for (int mi = 0; mi < 4; ++mi)
                    LDSM4(af[mi], AB + aoff + (uint32_t)(mi * 16 * PA * 2) + kb2);
                #pragma unroll
                for (int mi = 0; mi < 4; ++mi)
                    #pragma unroll
                    for (int ni = 0; ni < 8; ++ni)
                        MMA_F16(acc[mi][ni], af[mi],
                                bfr[ni >> 1][(ni & 1) * 2],
                                bfr[ni >> 1][(ni & 1) * 2 + 1]);
            }
            __syncthreads();
        }

        // ---- epilogue: sector-aligned permuted stores (R9 layout),
        //      shifted into this CTA's N-half.
        const int g = lane >> 2;
        const int q = lane & 3;
        const int cbase = nhalf * 128 + wn + q * 4;
        #pragma unroll
        for (int mi = 0; mi < 4; ++mi) {
            const size_t rbase = (size_t)(tile * MTILE + wm + mi * 16);
            float* p0 = out + (rbase + g)     * OUTF + cbase;
            float* p1 = out + (rbase + g + 8) * OUTF + cbase;
            #pragma unroll
            for (int j = 0; j < 4; ++j) {
                asm volatile("st.global.cs.v4.f32 [%0], {%1,%2,%3,%4};"
                             :: "l"(p0 + j * 16),
                                "f"(acc[mi][2*j][0]), "f"(acc[mi][2*j][1]),
                                "f"(acc[mi][2*j+1][0]), "f"(acc[mi][2*j+1][1]));
                asm volatile("st.global.cs.v4.f32 [%0], {%1,%2,%3,%4};"
                             :: "l"(p1 + j * 16),
                                "f"(acc[mi][2*j][2]), "f"(acc[mi][2*j][3]),
                                "f"(acc[mi][2*j+1][2]), "f"(acc[mi][2*j+1][3]));
            }
        }
    }
}

// ---------------------------------------------------------------------------
extern "C" void kernel_launch(void* const* d_in, const int* in_sizes, int n_in,
                              void* d_out, int out_size) {
    const float* x = (const float*)d_in[0];
    const float* w = (const float*)d_in[1];
    if (n_in >= 2 && in_sizes[0] < in_sizes[1]) {  // defensive: x is the big one
        const float* t = x; x = w; w = t;
    }
    float* out = (float*)d_out;

    prep_k<<<256, 256>>>(w);

    cudaFuncSetAttribute(bgemm_kernel,
                         cudaFuncAttributeMaxDynamicSharedMemorySize, SMEM_TOTAL);
    bgemm_kernel<<<2 * GRID, THREADS, SMEM_TOTAL>>>(x, out);
}

// round 13
// speedup vs baseline: 1.4071x; 1.1648x over previous
#include <cuda_runtime.h>
#include <cuda_fp16.h>
#include <cstdint>

// ============================================================================
// y = x @ W_binT - rowmean(y),  B=131072, IN=OUT=256.
// Trick 1: fold mean into weights: W' = W_bin - c/256 (EXACT in fp16).
// Trick 2: single fp16 pass for x (rel err ~2e-4 << 1e-3).
// R12 = R9 core (best: 69.5us kernel) + overhead harvest:
//   - prep: 64 blocks x float4 reads (4 cols/block) + redux.sync (~2us -> ~0.8)
//   - branch-free clamped LDG prefetch guards (removes 4 BSSY/BSYNC per tile)
// Structural ledger R5-R11: occupancy/barriers/frag-pipelining/no-smem/2-CTA
// all falsified; ~250 TF/s mma.sync ceiling is RF-bound (fp32 acc, 64x64 tile).
// ============================================================================

static constexpr int INF    = 256;
static constexpr int OUTF   = 256;
static constexpr int BATCH  = 131072;
static constexpr int MTILE  = 128;
static constexpr int NTILES = BATCH / MTILE;   // 1024
static constexpr int GRID   = 148;
static constexpr int THREADS = 256;

static constexpr int PW = 264;   // W smem pitch (halfs), conflict-free for ldmatrix
static constexpr int PA = 72;    // A smem pitch (halfs), conflict-free for ldmatrix
static constexpr int WBYTES = OUTF * PW * 2;        // 135168
static constexpr int ABYTES = MTILE * PA * 2;       // 18432
static constexpr int SMEM_TOTAL = WBYTES + 2 * ABYTES;  // 172032

__device__ __half g_wprep[OUTF * PW];   // mean-folded W', row-permuted

// ---------------------------------------------------------------------------
// fused prep, 4 columns per block (64 blocks x 256 threads).
// thread t = output row o; reads w[o][c0..c0+3] as one float4 (coalesced per
// row), warp-reduces the 4 column counts via redux.sync, then writes the
// mean-folded values at the R9-permuted row position (8B contiguous).
//  ROW permutation (sector-aligned epilogue):
//    rem=o&63: j=rem>>4, q=(rem>>2)&3, e=rem&3
//    pos = (o&~63) | (j*16 + (e>>1)*8 + q*2 + (e&1))
// ---------------------------------------------------------------------------
__global__ void prep_k(const float* __restrict__ w) {
    __shared__ int wred[4][8];
    __shared__ float csc[4];
    const int c0   = blockIdx.x * 4;
    const int t    = threadIdx.x;
    const int lane = t & 31, wid = t >> 5;

    const float4 v = *reinterpret_cast<const float4*>(w + t * INF + c0);
    const int b0 = v.x > 0.8f, b1 = v.y > 0.8f, b2 = v.z > 0.8f, b3 = v.w > 0.8f;

    const int s0 = __reduce_add_sync(0xffffffffu, b0);
    const int s1 = __reduce_add_sync(0xffffffffu, b1);
    const int s2 = __reduce_add_sync(0xffffffffu, b2);
    const int s3 = __reduce_add_sync(0xffffffffu, b3);
    if (lane == 0) {
        wred[0][wid] = s0; wred[1][wid] = s1;
        wred[2][wid] = s2; wred[3][wid] = s3;
    }
    __syncthreads();
    if (t < 4) {
        int s = 0;
        #pragma unroll
        for (int jj = 0; jj < 8; ++jj) s += wred[t][jj];
        csc[t] = (float)s * (1.0f / 256.0f);
    }
    __syncthreads();

    const int rem = t & 63;
    const int j = rem >> 4;
    const int q = (rem >> 2) & 3;
    const int e = rem & 3;
    const int pos = (t & ~63) | (j * 16 + (e >> 1) * 8 + q * 2 + (e & 1));
    __half2* dst = reinterpret_cast<__half2*>(&g_wprep[pos * PW + c0]);
    dst[0] = __floats2half2_rn((float)b0 - csc[0], (float)b1 - csc[1]);
    dst[1] = __floats2half2_rn((float)b2 - csc[2], (float)b3 - csc[3]);
}

// ---------------------------------------------------------------------------
// main GEMM (R9 core, guards clamped)
// ---------------------------------------------------------------------------
#define MMA_F16(c, a, b0, b1)                                                  \
    asm volatile(                                                              \
        "mma.sync.aligned.m16n8k16.row.col.f32.f16.f16.f32 "                   \
        "{%0,%1,%2,%3},{%4,%5,%6,%7},{%8,%9},{%0,%1,%2,%3};"                   \
        : "+f"((c)[0]), "+f"((c)[1]), "+f"((c)[2]), "+f"((c)[3])               \
        : "r"((a)[0]), "r"((a)[1]), "r"((a)[2]), "r"((a)[3]),                  \
          "r"(b0), "r"(b1))

#define LDSM4(r, addr)                                                         \
    asm volatile("ldmatrix.sync.aligned.m8n8.x4.shared.b16 {%0,%1,%2,%3}, [%4];" \
        : "=r"((r)[0]), "=r"((r)[1]), "=r"((r)[2]), "=r"((r)[3]) : "r"(addr))

__global__ void __launch_bounds__(THREADS, 1)
bgemm_kernel(const float* __restrict__ x, float* __restrict__ out)
{
    extern __shared__ char smem[];
    const int tid  = threadIdx.x;
    const int lane = tid & 31;
    const int wid  = tid >> 5;
    const int wm   = (wid & 1) * 64;   // warp m-offset (2-way)
    const int wn   = (wid >> 1) * 64;  // warp n-offset (4-way)

    // ---- resident W' into smem (whole kernel lifetime)
    {
        const uint4* src = reinterpret_cast<const uint4*>(g_wprep);
        uint4* dst = reinterpret_cast<uint4*>(smem);
        for (int idx = tid; idx < WBYTES / 16; idx += THREADS)
            dst[idx] = src[idx];
    }

    uint32_t sb;
    asm("{ .reg .u64 t; cvta.to.shared.u64 t, %1; cvt.u32.u64 %0, t; }"
        : "=r"(sb) : "l"(smem));
    const uint32_t ABUF[2] = { sb + WBYTES, sb + WBYTES + ABYTES };

    // per-thread ldmatrix source offsets (bytes)
    const uint32_t aoff =
        (uint32_t)((wm + (lane & 15)) * PA + (lane >> 4) * 8) * 2u;
    const uint32_t boff =
        (uint32_t)((wn + ((lane >> 4) & 1) * 8 + (lane & 7)) * PW +
                   ((lane >> 3) & 1) * 8) * 2u;

    // flat-index x mapping: 2048 float4 per 128x64 chunk, 256 threads ->
    // 8 float4/thread: row = (tid>>4) + 16*j, col4 = tid&15.
    const int arow0 = tid >> 4;         // 0..15
    const int acol4 = tid & 15;         // 0..15

    float4 xr[8];

    // clamped (branch-free) chunk load: out-of-range tiles re-read the last
    // valid tile; results are discarded, so correctness is unaffected.
    auto ldg_chunk = [&](int nt, int nc) {
        if (nt > NTILES - 1) nt = NTILES - 1;
        const float* gp = x + ((size_t)nt * MTILE + arow0) * INF
                           + nc * 64 + acol4 * 4;
        #pragma unroll
        for (int j = 0; j < 8; ++j) {
            float4 v;
            asm volatile("ld.global.cs.v4.f32 {%0,%1,%2,%3}, [%4];"
                         : "=f"(v.x), "=f"(v.y), "=f"(v.z), "=f"(v.w)
                         : "l"(gp + (size_t)j * 16 * INF));
            xr[j] = v;
        }
    };
    auto sts_chunk = [&](uint32_t ab) {
        const uint32_t base = ab + (uint32_t)(arow0 * PA + acol4 * 4) * 2u;
        #pragma unroll
        for (int j = 0; j < 8; ++j) {
            uint32_t h0, h1;
            asm("cvt.rn.f16x2.f32 %0, %1, %2;" : "=r"(h0) : "f"(xr[j].y), "f"(xr[j].x));
            asm("cvt.rn.f16x2.f32 %0, %1, %2;" : "=r"(h1) : "f"(xr[j].w), "f"(xr[j].z));
            asm volatile("st.shared.v2.b32 [%0], {%1,%2};"
                         :: "r"(base + (uint32_t)(j * 16 * PA) * 2u), "r"(h0), "r"(h1));
        }
    };

    // prologue: chunk0 -> buf0; preload chunk1 regs
    ldg_chunk(blockIdx.x, 0);
    sts_chunk(ABUF[0]);
    ldg_chunk(blockIdx.x, 1);
    __syncthreads();

    for (int tile = blockIdx.x; tile < NTILES; tile += GRID) {
        float acc[4][8][4];
        #pragma unroll
        for (int a = 0; a < 4; ++a)
            #pragma unroll
            for (int b = 0; b < 8; ++b)
                #pragma unroll
                for (int c = 0; c < 4; ++c) acc[a][b][c] = 0.0f;

        #pragma unroll
        for (int ch = 0; ch < 4; ++ch) {
            // STS chunk ch+1 (regs already loaded) into the other buffer
            sts_chunk(ABUF[(ch + 1) & 1]);

            // prefetch regs for chunk ch+2 (clamped past the end)
            {
                int nt = tile, nc = ch + 2;
                if (nc >= 4) { nc -= 4; nt += GRID; }
                ldg_chunk(nt, nc);
            }

            // MMA over chunk ch (4 k16-steps) from buf[ch&1]
            const uint32_t AB  = ABUF[ch & 1];
            const uint32_t bko = (uint32_t)(ch * 64) * 2u;
            #pragma unroll
            for (int ks = 0; ks < 4; ++ks) {
                const uint32_t kb2 = (uint32_t)(ks * 16) * 2u;
                uint32_t bfr[4][4];
                #pragma unroll
                for (int np = 0; np < 4; ++np)
                    LDSM4(bfr[np], sb + boff + (uint32_t)(np * 16 * PW * 2) + bko + kb2);
                uint32_t af[4][4];
                #pragma unroll
                for (int mi = 0; mi < 4; ++mi)
                    LDSM4(af[mi], AB + aoff + (uint32_t)(mi * 16 * PA * 2) + kb2);
                #pragma unroll
                for (int mi = 0; mi < 4; ++mi)
                    #pragma unroll
                    for (int ni = 0; ni < 8; ++ni)
                        MMA_F16(acc[mi][ni], af[mi],
                                bfr[ni >> 1][(ni & 1) * 2],
                                bfr[ni >> 1][(ni & 1) * 2 + 1]);
            }
            __syncthreads();
        }

        // ---- epilogue: sector-aligned permuted stores (R9 layout).
        const int g = lane >> 2;
        const int q = lane & 3;
        #pragma unroll
        for (int mi = 0; mi < 4; ++mi) {
            const size_t rbase = (size_t)(tile * MTILE + wm + mi * 16);
            float* p0 = out + (rbase + g)     * OUTF + wn + q * 4;
            float* p1 = out + (rbase + g + 8) * OUTF + wn + q * 4;
            #pragma unroll
            for (int j = 0; j < 4; ++j) {
                asm volatile("st.global.cs.v4.f32 [%0], {%1,%2,%3,%4};"
                             :: "l"(p0 + j * 16),
                                "f"(acc[mi][2*j][0]), "f"(acc[mi][2*j][1]),
                                "f"(acc[mi][2*j+1][0]), "f"(acc[mi][2*j+1][1]));
                asm volatile("st.global.cs.v4.f32 [%0], {%1,%2,%3,%4};"
                             :: "l"(p1 + j * 16),
                                "f"(acc[mi][2*j][2]), "f"(acc[mi][2*j][3]),
                                "f"(acc[mi][2*j+1][2]), "f"(acc[mi][2*j+1][3]));
            }
        }
    }
}

// ---------------------------------------------------------------------------
extern "C" void kernel_launch(void* const* d_in, const int* in_sizes, int n_in,
                              void* d_out, int out_size) {
    const float* x = (const float*)d_in[0];
    const float* w = (const float*)d_in[1];
    if (n_in >= 2 && in_sizes[0] < in_sizes[1]) {  // defensive: x is the big one
        const float* t = x; x = w; w = t;
    }
    float* out = (float*)d_out;

    prep_k<<<64, 256>>>(w);

    cudaFuncSetAttribute(bgemm_kernel,
                         cudaFuncAttributeMaxDynamicSharedMemorySize, SMEM_TOTAL);
    bgemm_kernel<<<GRID, THREADS, SMEM_TOTAL>>>(x, out);
}